// round 14
// baseline (speedup 1.0000x reference)
#include <cuda_runtime.h>
#include <math.h>
#include <stdint.h>

#define KK 128
#define DD 64
#define BM 128
#define PADX 66                 // ull stride per sX row (even -> 16B-aligned pairs)
#define LOG2PI 1.8378770664093454835
#define NTHREADS 512

typedef unsigned long long ull;

// weights packed (w2=-0.5*nb, w1=tau*nb), pair layout [kp=d/2][k][d&1]
__device__ ull    g_wcomb[DD * KK];
__device__ float  g_A[KK];
__device__ double g_kl;
__device__ double g_ll;
__device__ unsigned g_cnt;
__device__ double g_estick[KK], g_e1m[KK], g_base[KK], g_klk[KK];

// ---------------------------------------------------------------- helpers
__device__ __forceinline__ ull pack2(float lo, float hi) {
    return (ull)__float_as_uint(lo) | ((ull)__float_as_uint(hi) << 32);
}

__device__ __forceinline__ void ffma2(ull& acc, ull a, ull b) {
    asm("fma.rn.f32x2 %0, %1, %2, %3;" : "=l"(acc) : "l"(a), "l"(b), "l"(acc));
}

__device__ float dgf(float x) {    // digamma, float (abs err ~1e-7)
    float s = 0.0f;
    while (x < 8.0f) { s -= 1.0f / x; x += 1.0f; }
    float inv = 1.0f / x, i2 = inv * inv;
    float r = logf(x) - 0.5f * inv
        - i2 * (8.3333333e-2f - i2 * (8.3333333e-3f - i2 * (3.9682540e-3f
          - i2 * (4.1666667e-3f - i2 * 7.5757576e-3f))));
    return r + s;
}

// ---------------------------------------------------------------- setup, stage 1
// one block per k (128 blocks), one thread per d (64 threads); float specials
__global__ void setup1_kernel(const float* __restrict__ nu, const float* __restrict__ nv,
                              const float* __restrict__ ntau, const float* __restrict__ nc,
                              const float* __restrict__ nn, const float* __restrict__ nB) {
    __shared__ double sred[3][2];
    int k = blockIdx.x, d = threadIdx.x;
    int lane = d & 31, warp = d >> 5;

    float c = nc[k];
    float n = nn[k] - (float)DD - 2.0f;

    float t   = ntau[k * DD + d] / c;
    float B   = nB[k * DD + d] - c * t * t;
    float nbv = n / B;
    g_wcomb[(d >> 1) * (2 * KK) + (k << 1) + (d & 1)]
        = pack2(-0.5f * nbv, t * nbv);

    double logb1 = (double)logf(0.5f * B);
    double t2nb  = (double)(t * t * nbv);
    double rat   = (double)((0.5f - 0.5f * B) / (0.5f * B));

    #pragma unroll
    for (int off = 16; off > 0; off >>= 1) {
        logb1 += __shfl_down_sync(0xffffffffu, logb1, off);
        t2nb  += __shfl_down_sync(0xffffffffu, t2nb,  off);
        rat   += __shfl_down_sync(0xffffffffu, rat,   off);
    }
    if (lane == 0) { sred[0][warp] = logb1; sred[1][warp] = t2nb; sred[2][warp] = rat; }
    __syncthreads();

    if (d == 0) {
        double SlogB = sred[0][0] + sred[0][1];
        double St2   = sred[1][0] + sred[1][1];
        double Srat  = sred[2][0] + sred[2][1];

        float  a1f = 0.5f * n;
        double a1 = (double)a1f, a0g = 0.5 * ((double)DD + 2.0), b0g = 0.5;
        double dga1 = (double)dgf(a1f);
        double lga1 = (double)lgammaf(a1f);
        double lga0g = (double)lgammaf((float)a0g);

        double e_log_det = (double)DD * dga1 - SlogB;
        double klg = (double)DD * ((a1 - a0g) * dga1 - lga1 + lga0g - a0g * log(b0g))
                   + a0g * SlogB + a1 * Srat;
        double kln = 0.5 * ((double)DD * ((double)logf(c) + 1.0 / (double)c - 1.0) + St2);

        float u = nu[k] + 1.0f, v = nv[k] + 1.0f;
        double dgu = (double)dgf(u), dgv = (double)dgf(v), dguv = (double)dgf(u + v);
        double klb = (double)lgammaf(u + v) - (double)lgammaf(u) - (double)lgammaf(v)
                   + ((double)u - 1.0) * dgu + ((double)v - 1.0) * dgv
                   + (2.0 - (double)u - (double)v) * dguv;

        g_estick[k] = dgu - dguv;
        g_e1m[k]    = dgv - dguv;
        g_base[k]   = 0.5 * (e_log_det - (double)DD * LOG2PI - St2
                             - (double)DD / (double)c);
        g_klk[k]    = klb + klg + kln;
    }
}

// ---------------------------------------------------------------- setup, stage 2 (smem, fast)
__global__ void setup2_kernel() {
    __shared__ double sh[KK], pre[KK], red[KK];
    int k = threadIdx.x;
    sh[k]  = g_e1m[k];
    red[k] = g_klk[k];
    __syncthreads();
    if (k == 0) {
        double a = 0.0;
        for (int j = 0; j < KK; j++) { pre[j] = a; a += sh[j]; }
    }
    __syncthreads();
    g_A[k] = (float)(g_estick[k] + pre[k] + g_base[k]);
    __syncthreads();
    for (int off = KK / 2; off > 0; off >>= 1) {
        if (k < off) red[k] += red[k + off];
        __syncthreads();
    }
    if (k == 0) { g_kl = red[0]; g_ll = 0.0; g_cnt = 0u; }
}

// ---------------------------------------------------------------- main GEMM+softmax
__global__ void __launch_bounds__(NTHREADS, 1)
main_kernel(const float* __restrict__ x, float* __restrict__ out, int ntiles,
            long long outidx) {
    extern __shared__ ull smem[];
    ull*    sW  = smem;                           // [32][128][2] weight pairs
    ull*    sX0 = smem + DD * KK;                 // double-buffered x tiles
    ull*    sX1 = sX0 + BM * PADX;
    float*  sA  = (float*)(sX1 + BM * PADX);
    double* dll = (double*)(sA + KK);

    int tid = threadIdx.x;
    int tx = tid & 31, ty = tid >> 5;             // warp ty owns rows ty*8..+7

    // stage weights + A once per block
    #pragma unroll
    for (int i = tid; i < DD * KK; i += NTHREADS) sW[i] = g_wcomb[i];
    if (tid < KK) sA[tid] = g_A[tid];

    // stage first tile into buffer 0
    int tile = blockIdx.x;
    if (tile < ntiles) {
        const float4* xg = (const float4*)(x + (size_t)tile * BM * DD);
        #pragma unroll
        for (int p4 = 0; p4 < 4; p4++) {
            int q = tid + NTHREADS * p4;          // 2048 float4 per tile
            int r = q >> 4, d4 = (q & 15) << 2;
            float4 vv = xg[q];
            ull* dst = sX0 + r * PADX + d4;
            dst[0] = pack2(vv.x * vv.x, vv.x);
            dst[1] = pack2(vv.y * vv.y, vv.y);
            dst[2] = pack2(vv.z * vv.z, vv.z);
            dst[3] = pack2(vv.w * vv.w, vv.w);
        }
    }
    __syncthreads();

    // hoist per-thread softmax constants
    float aj[4];
    #pragma unroll
    for (int j = 0; j < 4; j++) aj[j] = sA[tx + 32 * j];

    double llacc = 0.0;
    int p = 0;

    for (; tile < ntiles; tile += gridDim.x) {
        ull* sX = p ? sX1 : sX0;

        ull acc[8][4];
        #pragma unroll
        for (int i = 0; i < 8; i++)
            #pragma unroll
            for (int j = 0; j < 4; j++) acc[i][j] = 0ULL;

        const ull* xrow = sX + (ty * 8) * PADX;
        #pragma unroll 2
        for (int kp = 0; kp < DD / 2; kp++) {
            ulonglong2 wv[4];
            const ull* wrow = sW + kp * (2 * KK) + tx * 2;
            #pragma unroll
            for (int j = 0; j < 4; j++)
                wv[j] = *(const ulonglong2*)&wrow[j * 64];
            #pragma unroll
            for (int i = 0; i < 8; i++) {
                ulonglong2 xv = *(const ulonglong2*)&xrow[i * PADX + 2 * kp];
                #pragma unroll
                for (int j = 0; j < 4; j++) ffma2(acc[i][j], wv[j].x, xv.x);
                #pragma unroll
                for (int j = 0; j < 4; j++) ffma2(acc[i][j], wv[j].y, xv.y);
            }
        }

        // fused softmax: row ty*8+i fully owned by warp ty (32 lanes x 4 cols)
        int rowbase = tile * BM;
        #pragma unroll
        for (int i = 0; i < 8; i++) {
            int row = ty * 8 + i;
            float lg[4];
            float m = -3.402823466e+38f;
            #pragma unroll
            for (int j = 0; j < 4; j++) {
                ull a = acc[i][j];
                float lo = __uint_as_float((unsigned)a);
                float hi = __uint_as_float((unsigned)(a >> 32));
                lg[j] = lo + hi + aj[j];
                m = fmaxf(m, lg[j]);
            }
            #pragma unroll
            for (int o = 16; o > 0; o >>= 1)
                m = fmaxf(m, __shfl_xor_sync(0xffffffffu, m, o));
            float s = 0.f;
            #pragma unroll
            for (int j = 0; j < 4; j++) { lg[j] = __expf(lg[j] - m); s += lg[j]; }
            #pragma unroll
            for (int o = 16; o > 0; o >>= 1)
                s += __shfl_xor_sync(0xffffffffu, s, o);
            float inv = 1.0f / s;
            float* orow = out + (size_t)(rowbase + row) * KK;
            #pragma unroll
            for (int j = 0; j < 4; j++) orow[tx + 32 * j] = lg[j] * inv;
            if (tx == 0) llacc += (double)(m + __logf(s));
        }

        // stage next tile into the other buffer (overlaps epilogue drain)
        int nxt = tile + gridDim.x;
        if (nxt < ntiles) {
            ull* sN = p ? sX0 : sX1;
            const float4* xg = (const float4*)(x + (size_t)nxt * BM * DD);
            #pragma unroll
            for (int q4 = 0; q4 < 4; q4++) {
                int q = tid + NTHREADS * q4;
                int r = q >> 4, d4 = (q & 15) << 2;
                float4 vv = xg[q];
                ull* dst = sN + r * PADX + d4;
                dst[0] = pack2(vv.x * vv.x, vv.x);
                dst[1] = pack2(vv.y * vv.y, vv.y);
                dst[2] = pack2(vv.z * vv.z, vv.z);
                dst[3] = pack2(vv.w * vv.w, vv.w);
            }
        }
        __syncthreads();
        p ^= 1;
    }

    if (tx == 0) dll[ty] = llacc;
    __syncthreads();
    if (tid == 0) {
        double t = 0.0;
        #pragma unroll
        for (int i = 0; i < 16; i++) t += dll[i];
        atomicAdd(&g_ll, t);
        __threadfence();
        unsigned old = atomicAdd(&g_cnt, 1u);
        if (old == gridDim.x - 1) {             // last block finalizes ELBO
            __threadfence();
            double ll = *((volatile double*)&g_ll);
            out[outidx] = (float)(g_kl - ll);
        }
    }
}

// ---------------------------------------------------------------- launch
extern "C" void kernel_launch(void* const* d_in, const int* in_sizes, int n_in,
                              void* d_out, int out_size) {
    const float* x    = (const float*)d_in[0];
    const float* nu   = (const float*)d_in[1];
    const float* nv   = (const float*)d_in[2];
    const float* ntau = (const float*)d_in[3];
    const float* nc   = (const float*)d_in[4];
    const float* nn   = (const float*)d_in[5];
    const float* nB   = (const float*)d_in[6];

    int K = in_sizes[1];
    int D = in_sizes[3] / K;
    int N = in_sizes[0] / D;
    int ntiles = N / BM;
    int grid = ntiles < 148 ? ntiles : 148;

    size_t smbytes = (size_t)(DD * KK + 2 * BM * PADX) * 8 + KK * 4 + 16 * 8;
    cudaFuncSetAttribute(main_kernel, cudaFuncAttributeMaxDynamicSharedMemorySize,
                         (int)smbytes);

    setup1_kernel<<<KK, DD>>>(nu, nv, ntau, nc, nn, nB);
    setup2_kernel<<<1, KK>>>();
    main_kernel<<<grid, NTHREADS, smbytes>>>(x, (float*)d_out, ntiles,
                                             (long long)out_size - 1);
}

// round 15
// speedup vs baseline: 1.5664x; 1.5664x over previous
#include <cuda_runtime.h>
#include <math.h>
#include <stdint.h>

#define KK 128
#define DD 64
#define BM 128
#define PADX 66                 // ull stride per sX row (even -> 16B-aligned pairs)
#define LOG2PI 1.8378770664093454835
#define NTHREADS 512

typedef unsigned long long ull;

// weights packed (w2=-0.5*nb, w1=tau*nb), pair layout [kp=d/2][k][d&1]
__device__ ull    g_wcomb[DD * KK];
__device__ float  g_A[KK];
__device__ double g_kl;
__device__ double g_ll;
__device__ unsigned g_cnt;
__device__ double g_estick[KK], g_e1m[KK], g_base[KK], g_klk[KK];

// ---------------------------------------------------------------- helpers
__device__ __forceinline__ ull pack2(float lo, float hi) {
    return (ull)__float_as_uint(lo) | ((ull)__float_as_uint(hi) << 32);
}

__device__ __forceinline__ void ffma2(ull& acc, ull a, ull b) {
    asm("fma.rn.f32x2 %0, %1, %2, %3;" : "=l"(acc) : "l"(a), "l"(b), "l"(acc));
}

__device__ float dgf(float x) {    // digamma, float (abs err ~1e-7)
    float s = 0.0f;
    while (x < 8.0f) { s -= 1.0f / x; x += 1.0f; }
    float inv = 1.0f / x, i2 = inv * inv;
    float r = logf(x) - 0.5f * inv
        - i2 * (8.3333333e-2f - i2 * (8.3333333e-3f - i2 * (3.9682540e-3f
          - i2 * (4.1666667e-3f - i2 * 7.5757576e-3f))));
    return r + s;
}

// ---------------------------------------------------------------- setup, stage 1
// one block per k (128 blocks), one thread per d (64 threads); float specials
__global__ void setup1_kernel(const float* __restrict__ nu, const float* __restrict__ nv,
                              const float* __restrict__ ntau, const float* __restrict__ nc,
                              const float* __restrict__ nn, const float* __restrict__ nB) {
    __shared__ double sred[3][2];
    int k = blockIdx.x, d = threadIdx.x;
    int lane = d & 31, warp = d >> 5;

    float c = nc[k];
    float n = nn[k] - (float)DD - 2.0f;

    float t   = ntau[k * DD + d] / c;
    float B   = nB[k * DD + d] - c * t * t;
    float nbv = n / B;
    g_wcomb[(d >> 1) * (2 * KK) + (k << 1) + (d & 1)]
        = pack2(-0.5f * nbv, t * nbv);

    double logb1 = (double)logf(0.5f * B);
    double t2nb  = (double)(t * t * nbv);
    double rat   = (double)((0.5f - 0.5f * B) / (0.5f * B));

    #pragma unroll
    for (int off = 16; off > 0; off >>= 1) {
        logb1 += __shfl_down_sync(0xffffffffu, logb1, off);
        t2nb  += __shfl_down_sync(0xffffffffu, t2nb,  off);
        rat   += __shfl_down_sync(0xffffffffu, rat,   off);
    }
    if (lane == 0) { sred[0][warp] = logb1; sred[1][warp] = t2nb; sred[2][warp] = rat; }
    __syncthreads();

    if (d == 0) {
        double SlogB = sred[0][0] + sred[0][1];
        double St2   = sred[1][0] + sred[1][1];
        double Srat  = sred[2][0] + sred[2][1];

        float  a1f = 0.5f * n;
        double a1 = (double)a1f, a0g = 0.5 * ((double)DD + 2.0), b0g = 0.5;
        double dga1 = (double)dgf(a1f);
        double lga1 = (double)lgammaf(a1f);
        double lga0g = (double)lgammaf((float)a0g);

        double e_log_det = (double)DD * dga1 - SlogB;
        double klg = (double)DD * ((a1 - a0g) * dga1 - lga1 + lga0g - a0g * log(b0g))
                   + a0g * SlogB + a1 * Srat;
        double kln = 0.5 * ((double)DD * ((double)logf(c) + 1.0 / (double)c - 1.0) + St2);

        float u = nu[k] + 1.0f, v = nv[k] + 1.0f;
        double dgu = (double)dgf(u), dgv = (double)dgf(v), dguv = (double)dgf(u + v);
        double klb = (double)lgammaf(u + v) - (double)lgammaf(u) - (double)lgammaf(v)
                   + ((double)u - 1.0) * dgu + ((double)v - 1.0) * dgv
                   + (2.0 - (double)u - (double)v) * dguv;

        g_estick[k] = dgu - dguv;
        g_e1m[k]    = dgv - dguv;
        g_base[k]   = 0.5 * (e_log_det - (double)DD * LOG2PI - St2
                             - (double)DD / (double)c);
        g_klk[k]    = klb + klg + kln;
    }
}

// ---------------------------------------------------------------- setup, stage 2 (smem, fast)
__global__ void setup2_kernel() {
    __shared__ double sh[KK], pre[KK], red[KK];
    int k = threadIdx.x;
    sh[k]  = g_e1m[k];
    red[k] = g_klk[k];
    __syncthreads();
    if (k == 0) {
        double a = 0.0;
        for (int j = 0; j < KK; j++) { pre[j] = a; a += sh[j]; }
    }
    __syncthreads();
    g_A[k] = (float)(g_estick[k] + pre[k] + g_base[k]);
    __syncthreads();
    for (int off = KK / 2; off > 0; off >>= 1) {
        if (k < off) red[k] += red[k + off];
        __syncthreads();
    }
    if (k == 0) { g_kl = red[0]; g_ll = 0.0; g_cnt = 0u; }
}

// ---------------------------------------------------------------- main GEMM+softmax
__global__ void __launch_bounds__(NTHREADS, 1)
main_kernel(const float* __restrict__ x, float* __restrict__ out, int ntiles,
            long long outidx) {
    extern __shared__ ull smem[];
    ull*    sW  = smem;                           // [32][128][2] weight pairs
    ull*    sX0 = smem + DD * KK;                 // double-buffered x tiles
    ull*    sX1 = sX0 + BM * PADX;
    float*  sA  = (float*)(sX1 + BM * PADX);
    double* dll = (double*)(sA + KK);

    int tid = threadIdx.x;
    int tx = tid & 31, ty = tid >> 5;             // warp ty owns rows ty*8..+7

    // stage weights + A once per block
    #pragma unroll
    for (int i = tid; i < DD * KK; i += NTHREADS) sW[i] = g_wcomb[i];
    if (tid < KK) sA[tid] = g_A[tid];

    // stage first tile into buffer 0
    int tile = blockIdx.x;
    if (tile < ntiles) {
        const float4* xg = (const float4*)(x + (size_t)tile * BM * DD);
        #pragma unroll
        for (int p4 = 0; p4 < 4; p4++) {
            int q = tid + NTHREADS * p4;          // 2048 float4 per tile
            int r = q >> 4, d4 = (q & 15) << 2;
            float4 vv = xg[q];
            ull* dst = sX0 + r * PADX + d4;
            dst[0] = pack2(vv.x * vv.x, vv.x);
            dst[1] = pack2(vv.y * vv.y, vv.y);
            dst[2] = pack2(vv.z * vv.z, vv.z);
            dst[3] = pack2(vv.w * vv.w, vv.w);
        }
    }
    __syncthreads();

    // hoist per-thread softmax constants
    float aj[4];
    #pragma unroll
    for (int j = 0; j < 4; j++) aj[j] = sA[tx + 32 * j];

    double llacc = 0.0;
    int p = 0;

    for (; tile < ntiles; tile += gridDim.x) {
        ull* sX = p ? sX1 : sX0;

        ull acc[8][4];
        #pragma unroll
        for (int i = 0; i < 8; i++)
            #pragma unroll
            for (int j = 0; j < 4; j++) acc[i][j] = 0ULL;

        const ull* xrow = sX + (ty * 8) * PADX;
        #pragma unroll 2
        for (int kp = 0; kp < DD / 2; kp++) {
            ulonglong2 wv[4];
            const ull* wrow = sW + kp * (2 * KK) + tx * 2;
            #pragma unroll
            for (int j = 0; j < 4; j++)
                wv[j] = *(const ulonglong2*)&wrow[j * 64];
            #pragma unroll
            for (int i = 0; i < 8; i++) {
                ulonglong2 xv = *(const ulonglong2*)&xrow[i * PADX + 2 * kp];
                #pragma unroll
                for (int j = 0; j < 4; j++) ffma2(acc[i][j], wv[j].x, xv.x);
                #pragma unroll
                for (int j = 0; j < 4; j++) ffma2(acc[i][j], wv[j].y, xv.y);
            }
        }

        // fused softmax: row ty*8+i fully owned by warp ty (32 lanes x 4 cols)
        int rowbase = tile * BM;
        #pragma unroll
        for (int i = 0; i < 8; i++) {
            int row = ty * 8 + i;
            float lg[4];
            #pragma unroll
            for (int j = 0; j < 4; j++) {
                ull a = acc[i][j];
                float lo = __uint_as_float((unsigned)a);
                float hi = __uint_as_float((unsigned)(a >> 32));
                lg[j] = lo + hi + aj[j];
            }
            float m = fmaxf(fmaxf(lg[0], lg[1]), fmaxf(lg[2], lg[3]));
            #pragma unroll
            for (int o = 16; o > 0; o >>= 1)
                m = fmaxf(m, __shfl_xor_sync(0xffffffffu, m, o));
            float s = 0.f;
            #pragma unroll
            for (int j = 0; j < 4; j++) { lg[j] = __expf(lg[j] - m); s += lg[j]; }
            #pragma unroll
            for (int o = 16; o > 0; o >>= 1)
                s += __shfl_xor_sync(0xffffffffu, s, o);
            float inv = __fdividef(1.0f, s);
            float* orow = out + (size_t)(rowbase + row) * KK;
            #pragma unroll
            for (int j = 0; j < 4; j++) orow[tx + 32 * j] = lg[j] * inv;
            if (tx == 0) llacc += (double)(m + __logf(s));
        }

        // stage next tile into the other buffer (overlaps epilogue drain)
        int nxt = tile + gridDim.x;
        if (nxt < ntiles) {
            ull* sN = p ? sX0 : sX1;
            const float4* xg = (const float4*)(x + (size_t)nxt * BM * DD);
            #pragma unroll
            for (int q4 = 0; q4 < 4; q4++) {
                int q = tid + NTHREADS * q4;
                int r = q >> 4, d4 = (q & 15) << 2;
                float4 vv = xg[q];
                ull* dst = sN + r * PADX + d4;
                dst[0] = pack2(vv.x * vv.x, vv.x);
                dst[1] = pack2(vv.y * vv.y, vv.y);
                dst[2] = pack2(vv.z * vv.z, vv.z);
                dst[3] = pack2(vv.w * vv.w, vv.w);
            }
        }
        __syncthreads();
        p ^= 1;
    }

    if (tx == 0) dll[ty] = llacc;
    __syncthreads();
    if (tid == 0) {
        double t = 0.0;
        #pragma unroll
        for (int i = 0; i < 16; i++) t += dll[i];
        atomicAdd(&g_ll, t);
        __threadfence();
        unsigned old = atomicAdd(&g_cnt, 1u);
        if (old == gridDim.x - 1) {             // last block finalizes ELBO
            __threadfence();
            double ll = *((volatile double*)&g_ll);
            out[outidx] = (float)(g_kl - ll);
        }
    }
}

// ---------------------------------------------------------------- launch
extern "C" void kernel_launch(void* const* d_in, const int* in_sizes, int n_in,
                              void* d_out, int out_size) {
    const float* x    = (const float*)d_in[0];
    const float* nu   = (const float*)d_in[1];
    const float* nv   = (const float*)d_in[2];
    const float* ntau = (const float*)d_in[3];
    const float* nc   = (const float*)d_in[4];
    const float* nn   = (const float*)d_in[5];
    const float* nB   = (const float*)d_in[6];

    int K = in_sizes[1];
    int D = in_sizes[3] / K;
    int N = in_sizes[0] / D;
    int ntiles = N / BM;
    int grid = ntiles < 148 ? ntiles : 148;

    size_t smbytes = (size_t)(DD * KK + 2 * BM * PADX) * 8 + KK * 4 + 16 * 8;
    cudaFuncSetAttribute(main_kernel, cudaFuncAttributeMaxDynamicSharedMemorySize,
                         (int)smbytes);

    setup1_kernel<<<KK, DD>>>(nu, nv, ntau, nc, nn, nB);
    setup2_kernel<<<1, KK>>>();
    main_kernel<<<grid, NTHREADS, smbytes>>>(x, (float*)d_out, ntiles,
                                             (long long)out_size - 1);
}